// round 1
// baseline (speedup 1.0000x reference)
#include <cuda_runtime.h>
#include <cuda_bf16.h>
#include <math.h>

// Problem constants (fixed shapes)
#define TOK   131072      // B*H*W = 8*128*128
#define CDIM  192
#define HID   768
#define QKVN  576
#define NHEAD 6
#define HD    32
#define WS    8
#define SS    4
#define NWIN  2048        // B * 16 * 16

// ---------------- scratch (device globals; no allocations allowed) ----------
__device__ float g_qkv[TOK * QKVN];      // window-ordered rows, cols: which*192 + head*32 + d
__device__ float g_attnout[TOK * CDIM];  // window-ordered rows, c = head*32 + d
__device__ float g_x1[TOK * CDIM];       // x + attn branch (global token order)
__device__ float g_h[TOK * HID];         // gelu(fc1) activations
__device__ float g_mu[TOK];
__device__ float g_rs[TOK];

// window-ordered row r -> global token row in x (applies roll(-ss) + partition)
__device__ __forceinline__ int map_win_to_global(int r) {
    int w = r >> 6, n = r & 63;
    int b = w >> 8, rem = w & 255;
    int wh = rem >> 4, ww = rem & 15;
    int i = n >> 3, j = n & 7;
    int h  = (wh * 8 + i + SS) & 127;
    int wc = (ww * 8 + j + SS) & 127;
    return (b << 14) + (h << 7) + wc;
}

// global token row r -> window-ordered row (win_reverse + roll(+ss) inverse)
__device__ __forceinline__ int map_global_to_win(int r) {
    int b = r >> 14, rem = r & 16383;
    int h = rem >> 7, wc = rem & 127;
    int hs  = (h  + 128 - SS) & 127;
    int wsc = (wc + 128 - SS) & 127;
    int wh = hs >> 3, i = hs & 7;
    int ww = wsc >> 3, j = wsc & 7;
    int w = (b << 8) + (wh << 4) + ww;
    int n = (i << 3) + j;
    return (w << 6) + n;
}

__device__ __forceinline__ float gelu_exact(float v) {
    return 0.5f * v * (1.0f + erff(v * 0.70710678118654752440f));
}

// ---------------- tiled GEMM with fused gather / LN / epilogues -------------
// C[M,N] = A'[M,K] @ B[K,N] + bias (+ residual / gelu), M=131072
// BM=128, BN=64, BK=16, 256 threads, 4x8 register tile.
// MODE: 0=QKV  1=PROJ  2=FC1(LN in, gelu out)  3=FC2(residual x1 -> d_out)
template<int KDIM, int NDIM, int MODE>
__global__ void __launch_bounds__(256) gemm_k(
    const float* __restrict__ Ain,
    const float* __restrict__ Bw,
    const float* __restrict__ bias,
    const float* __restrict__ resid,
    float* __restrict__ Cout,
    const float* __restrict__ gamma,
    const float* __restrict__ beta)
{
    __shared__ float As[16][128];
    __shared__ float Bs[16][64];
    __shared__ int   rowmap[128];
    __shared__ float smu[128], srs[128];

    const int tid = threadIdx.x;
    const int bm = blockIdx.y * 128;   // y-major over M so same-A blocks co-run (L2 reuse)
    const int bn = blockIdx.x * 64;

    const float* Aptr;
    if      constexpr (MODE == 0) Aptr = Ain;        // x (gathered)
    else if constexpr (MODE == 1) Aptr = g_attnout;  // gathered
    else if constexpr (MODE == 2) Aptr = g_x1;
    else                          Aptr = g_h;

    if (tid < 128) {
        int r = bm + tid;
        int src;
        if      constexpr (MODE == 0) src = map_win_to_global(r);
        else if constexpr (MODE == 1) src = map_global_to_win(r);
        else                          src = r;
        rowmap[tid] = src;
        if constexpr (MODE == 2) { smu[tid] = g_mu[r]; srs[tid] = g_rs[r]; }
    }
    __syncthreads();

    float acc[4][8];
    #pragma unroll
    for (int i = 0; i < 4; i++)
        #pragma unroll
        for (int j = 0; j < 8; j++) acc[i][j] = 0.f;

    const int tm = (tid >> 3) << 2;   // 0..124
    const int tn = (tid & 7) << 3;    // 0..56

    for (int k0 = 0; k0 < KDIM; k0 += 16) {
        // load A tile: 128x16 = 512 float4, 2 per thread
        #pragma unroll
        for (int l = 0; l < 2; l++) {
            int i   = tid + l * 256;
            int row = i >> 2;
            int cg  = (i & 3) << 2;
            const float* ap = Aptr + (long)rowmap[row] * KDIM + k0 + cg;
            float4 v = *(const float4*)ap;
            if constexpr (MODE == 2) {
                float mm = smu[row], rr = srs[row];
                v.x = (v.x - mm) * rr * __ldg(&gamma[k0+cg+0]) + __ldg(&beta[k0+cg+0]);
                v.y = (v.y - mm) * rr * __ldg(&gamma[k0+cg+1]) + __ldg(&beta[k0+cg+1]);
                v.z = (v.z - mm) * rr * __ldg(&gamma[k0+cg+2]) + __ldg(&beta[k0+cg+2]);
                v.w = (v.w - mm) * rr * __ldg(&gamma[k0+cg+3]) + __ldg(&beta[k0+cg+3]);
            }
            As[cg+0][row] = v.x; As[cg+1][row] = v.y;
            As[cg+2][row] = v.z; As[cg+3][row] = v.w;
        }
        // load B tile: 16x64 = 256 float4, 1 per thread
        {
            int krow = tid >> 4;
            int cg   = (tid & 15) << 2;
            *(float4*)&Bs[krow][cg] =
                *(const float4*)(Bw + (long)(k0 + krow) * NDIM + bn + cg);
        }
        __syncthreads();
        #pragma unroll
        for (int k = 0; k < 16; k++) {
            float4 a  = *(float4*)&As[k][tm];
            float4 b0 = *(float4*)&Bs[k][tn];
            float4 b1 = *(float4*)&Bs[k][tn + 4];
            float av[4] = {a.x, a.y, a.z, a.w};
            float bv[8] = {b0.x, b0.y, b0.z, b0.w, b1.x, b1.y, b1.z, b1.w};
            #pragma unroll
            for (int i = 0; i < 4; i++)
                #pragma unroll
                for (int j = 0; j < 8; j++) acc[i][j] += av[i] * bv[j];
        }
        __syncthreads();
    }

    // epilogue
    const int c0 = bn + tn;
    #pragma unroll
    for (int i = 0; i < 4; i++) {
        int r = bm + tm + i;
        float out[8];
        #pragma unroll
        for (int j = 0; j < 8; j++) out[j] = acc[i][j] + __ldg(&bias[c0 + j]);

        if constexpr (MODE == 0) {
            float4* dst = (float4*)&g_qkv[(long)r * QKVN + c0];
            dst[0] = make_float4(out[0], out[1], out[2], out[3]);
            dst[1] = make_float4(out[4], out[5], out[6], out[7]);
        } else if constexpr (MODE == 1) {
            const float4* rp = (const float4*)&resid[(long)r * CDIM + c0];
            float4 r0 = rp[0], r1 = rp[1];
            out[0]+=r0.x; out[1]+=r0.y; out[2]+=r0.z; out[3]+=r0.w;
            out[4]+=r1.x; out[5]+=r1.y; out[6]+=r1.z; out[7]+=r1.w;
            float4* dst = (float4*)&g_x1[(long)r * CDIM + c0];
            dst[0] = make_float4(out[0], out[1], out[2], out[3]);
            dst[1] = make_float4(out[4], out[5], out[6], out[7]);
        } else if constexpr (MODE == 2) {
            #pragma unroll
            for (int j = 0; j < 8; j++) out[j] = gelu_exact(out[j]);
            float4* dst = (float4*)&g_h[(long)r * HID + c0];
            dst[0] = make_float4(out[0], out[1], out[2], out[3]);
            dst[1] = make_float4(out[4], out[5], out[6], out[7]);
        } else {
            const float4* rp = (const float4*)&g_x1[(long)r * CDIM + c0];
            float4 r0 = rp[0], r1 = rp[1];
            out[0]+=r0.x; out[1]+=r0.y; out[2]+=r0.z; out[3]+=r0.w;
            out[4]+=r1.x; out[5]+=r1.y; out[6]+=r1.z; out[7]+=r1.w;
            float4* dst = (float4*)&Cout[(long)r * CDIM + c0];
            dst[0] = make_float4(out[0], out[1], out[2], out[3]);
            dst[1] = make_float4(out[4], out[5], out[6], out[7]);
        }
    }
}

// ---------------- attention: one block per (window, head) -------------------
__global__ void __launch_bounds__(64) attn_k(const float* __restrict__ rpb)
{
    const int w = blockIdx.x, head = blockIdx.y, t = threadIdx.x;
    __shared__ float sK[64][32];
    __shared__ float sV[64][32];
    __shared__ float sS[64][65];
    __shared__ float sRp[225];
    __shared__ int   sReg[64];

    const float* base = g_qkv + (long)w * 64 * QKVN + head * HD;
    #pragma unroll
    for (int l = 0; l < 8; l++) {           // 512 float4 / 64 threads
        int i = t + l * 64;
        int n = i >> 3, dg = (i & 7) << 2;
        *(float4*)&sK[n][dg] = *(const float4*)(base + (long)n * QKVN + CDIM     + dg);
        *(float4*)&sV[n][dg] = *(const float4*)(base + (long)n * QKVN + 2*CDIM   + dg);
    }
    for (int i = t; i < 225; i += 64) sRp[i] = rpb[i * NHEAD + head];
    {
        int rem = w & 255; int wh = rem >> 4, ww = rem & 15;
        int hs  = wh * 8 + (t >> 3);
        int wsc = ww * 8 + (t & 7);
        int rh = hs  < 120 ? 0 : (hs  < 124 ? 1 : 2);
        int rw = wsc < 120 ? 0 : (wsc < 124 ? 1 : 2);
        sReg[t] = rh * 3 + rw;
    }
    float qr[32];
    {
        const float* qp = g_qkv + ((long)w * 64 + t) * QKVN + head * HD;
        #pragma unroll
        for (int dg = 0; dg < 32; dg += 4) {
            float4 v = *(const float4*)(qp + dg);
            qr[dg] = v.x; qr[dg+1] = v.y; qr[dg+2] = v.z; qr[dg+3] = v.w;
        }
    }
    __syncthreads();

    const int i1 = t >> 3, j1 = t & 7;
    const int regt = sReg[t];
    const float scale = 0.17677669529663689f;  // 32^-0.5

    for (int m = 0; m < 64; m++) {
        float acc = 0.f;
        #pragma unroll
        for (int d4 = 0; d4 < 8; d4++) {
            float4 kk = *(const float4*)&sK[m][d4 * 4];
            acc += qr[d4*4+0]*kk.x + qr[d4*4+1]*kk.y + qr[d4*4+2]*kk.z + qr[d4*4+3]*kk.w;
        }
        int i2 = m >> 3, j2 = m & 7;
        float b = sRp[(i1 - i2 + 7) * 15 + (j1 - j2 + 7)];
        float msk = (sReg[m] == regt) ? 0.f : -100.f;
        sS[t][m] = acc * scale + b + msk;
    }
    // softmax over own row
    float mx = -1e30f;
    for (int m = 0; m < 64; m++) mx = fmaxf(mx, sS[t][m]);
    float sum = 0.f;
    for (int m = 0; m < 64; m++) { float e = __expf(sS[t][m] - mx); sS[t][m] = e; sum += e; }
    float inv = 1.f / sum;

    float acc[32];
    #pragma unroll
    for (int d = 0; d < 32; d++) acc[d] = 0.f;
    for (int m = 0; m < 64; m++) {
        float p = sS[t][m];
        #pragma unroll
        for (int d4 = 0; d4 < 8; d4++) {
            float4 vv = *(const float4*)&sV[m][d4 * 4];
            acc[d4*4+0] += p * vv.x; acc[d4*4+1] += p * vv.y;
            acc[d4*4+2] += p * vv.z; acc[d4*4+3] += p * vv.w;
        }
    }
    float* op = g_attnout + ((long)w * 64 + t) * CDIM + head * HD;
    #pragma unroll
    for (int dg = 0; dg < 32; dg += 4)
        *(float4*)(op + dg) = make_float4(acc[dg]*inv, acc[dg+1]*inv, acc[dg+2]*inv, acc[dg+3]*inv);
}

// ---------------- LayerNorm statistics (one warp per token) -----------------
__global__ void __launch_bounds__(256) ln_stats_k()
{
    int r = blockIdx.x * 8 + (threadIdx.x >> 5);
    int lane = threadIdx.x & 31;
    const float* p = g_x1 + (long)r * CDIM;
    float s = 0.f, ss = 0.f;
    #pragma unroll
    for (int k = 0; k < 6; k++) { float v = p[lane + k * 32]; s += v; ss += v * v; }
    #pragma unroll
    for (int o = 16; o; o >>= 1) {
        s  += __shfl_xor_sync(0xffffffffu, s,  o);
        ss += __shfl_xor_sync(0xffffffffu, ss, o);
    }
    if (lane == 0) {
        float muv = s * (1.f / 192.f);
        float var = ss * (1.f / 192.f) - muv * muv;
        g_mu[r] = muv;
        g_rs[r] = rsqrtf(var + 1e-5f);
    }
}

// ---------------- launch ----------------------------------------------------
extern "C" void kernel_launch(void* const* d_in, const int* in_sizes, int n_in,
                              void* d_out, int out_size)
{
    const float* x       = (const float*)d_in[0];
    const float* qkv_w   = (const float*)d_in[1];
    const float* qkv_b   = (const float*)d_in[2];
    const float* proj_w  = (const float*)d_in[3];
    const float* proj_b  = (const float*)d_in[4];
    const float* rpb     = (const float*)d_in[5];
    const float* norm2_g = (const float*)d_in[6];
    const float* norm2_b = (const float*)d_in[7];
    const float* mlp_w1  = (const float*)d_in[8];
    const float* mlp_b1  = (const float*)d_in[9];
    const float* mlp_w2  = (const float*)d_in[10];
    const float* mlp_b2  = (const float*)d_in[11];
    float* out = (float*)d_out;

    // 1) QKV projection (shift + window partition fused into row gather)
    gemm_k<192, 576, 0><<<dim3(9, 1024), 256>>>(x, qkv_w, qkv_b, nullptr, nullptr, nullptr, nullptr);
    // 2) windowed attention with rel-pos bias + shift mask
    attn_k<<<dim3(NWIN, NHEAD), 64>>>(rpb);
    // 3) output projection + reverse shift + residual -> x1
    gemm_k<192, 192, 1><<<dim3(3, 1024), 256>>>(nullptr, proj_w, proj_b, x, nullptr, nullptr, nullptr);
    // 4) LayerNorm stats on x1
    ln_stats_k<<<TOK / 8, 256>>>();
    // 5) LN-fused fc1 + exact GELU
    gemm_k<192, 768, 2><<<dim3(12, 1024), 256>>>(nullptr, mlp_w1, mlp_b1, nullptr, nullptr, norm2_g, norm2_b);
    // 6) fc2 + residual -> d_out
    gemm_k<768, 192, 3><<<dim3(3, 1024), 256>>>(nullptr, mlp_w2, mlp_b2, nullptr, out, nullptr, nullptr);
}

// round 3
// speedup vs baseline: 1.4166x; 1.4166x over previous
#include <cuda_runtime.h>
#include <cuda_bf16.h>
#include <mma.h>
#include <cstdint>
#include <math.h>

using namespace nvcuda;

// Problem constants (fixed shapes)
#define TOK   131072      // B*H*W = 8*128*128
#define CDIM  192
#define HID   768
#define QKVN  576
#define NHEAD 6
#define HD    32
#define SS    4
#define NWIN  2048        // B * 16 * 16

// GEMM tiling
#define BM 128
#define BN 64
#define BK 16
#define LDA 20            // A tile leading dim (floats), padded
#define LDB 72            // B tile leading dim
#define LDC 68            // C tile leading dim
#define A_STAGE_F (BM * LDA)          // 2560 floats
#define B_STAGE_F (BK * LDB)          // 1152 floats
#define AB_BYTES  (2 * A_STAGE_F * 4 + 2 * B_STAGE_F * 4)   // 29696
#define C_BYTES   (BM * LDC * 4)                            // 34816

// ---------------- scratch (device globals; no allocations allowed) ----------
__device__ float g_qkv[TOK * QKVN];      // window-ordered rows
__device__ float g_attnout[TOK * CDIM];  // window-ordered rows
__device__ float g_x1[TOK * CDIM];       // x + attn branch (global order)
__device__ float g_x1n[TOK * CDIM];      // LN(x1)*gamma + beta
__device__ float g_h[TOK * HID];         // gelu(fc1)

// ---------------- small helpers ----------------------------------------------
__device__ __forceinline__ uint32_t smem_u32(const void* p) {
    uint32_t a;
    asm("{ .reg .u64 t; cvta.to.shared.u64 t, %1; cvt.u32.u64 %0, t; }" : "=r"(a) : "l"(p));
    return a;
}
#define CP_ASYNC16(dst, src) \
    asm volatile("cp.async.cg.shared.global [%0], [%1], 16;" :: "r"(dst), "l"(src))
#define CP_COMMIT() asm volatile("cp.async.commit_group;" ::: "memory")
#define CP_WAIT(n)  asm volatile("cp.async.wait_group %0;" :: "n"(n) : "memory")

__device__ __forceinline__ int map_win_to_global(int r) {
    int w = r >> 6, n = r & 63;
    int b = w >> 8, rem = w & 255;
    int wh = rem >> 4, ww = rem & 15;
    int i = n >> 3, j = n & 7;
    int h  = (wh * 8 + i + SS) & 127;
    int wc = (ww * 8 + j + SS) & 127;
    return (b << 14) + (h << 7) + wc;
}
__device__ __forceinline__ float gelu_exact(float v) {
    return 0.5f * v * (1.0f + erff(v * 0.70710678118654752440f));
}

// ---------------- WMMA tf32 GEMM --------------------------------------------
// C[M,N] = A[M,K] @ B[K,N] (+bias, +epilogue), A row-major, B row-major.
// MODE: 0=QKV(gather A rows from x)  1=PROJ(scatter + residual -> g_x1)
//       2=FC1(gelu -> g_h)           3=FC2(+residual g_x1 -> Cout)
template<int KDIM, int NDIM, int MODE>
__global__ void __launch_bounds__(256) gemm_wmma(
    const float* __restrict__ A0,      // MODE0: x
    const float* __restrict__ Bw,      // weight [K][N] row-major (original layout)
    const float* __restrict__ bias,
    const float* __restrict__ resid,   // MODE1: x
    float* __restrict__ Cout)          // MODE3: final output
{
    __shared__ __align__(16) unsigned char smem[C_BYTES];   // C tile unions over A/B
    float* sA = (float*)smem;                       // [2][BM*LDA]
    float* sB = (float*)(smem + 2 * A_STAGE_F * 4); // [2][BK*LDB]
    float* sC = (float*)smem;

    const int tid = threadIdx.x;
    const int bm = blockIdx.y * BM;
    const int bn = blockIdx.x * BN;

    const float* Aptr;
    if      constexpr (MODE == 0) Aptr = A0;
    else if constexpr (MODE == 1) Aptr = g_attnout;
    else if constexpr (MODE == 2) Aptr = g_x1n;
    else                          Aptr = g_h;

    // A: 128 rows x 16 floats = 512 float4; 2 per thread (rows tid>>2 and +64)
    const int rA  = tid >> 2;
    const int cgA = (tid & 3) << 2;
    int gr0, gr1;
    if constexpr (MODE == 0) { gr0 = map_win_to_global(bm + rA); gr1 = map_win_to_global(bm + rA + 64); }
    else                     { gr0 = bm + rA;                    gr1 = bm + rA + 64; }
    // B: 16 k-rows x 64 floats = 256 float4; 1 per thread
    const int krB = tid >> 4;
    const int cgB = (tid & 15) << 2;

    const uint32_t sAaddr = smem_u32(sA);
    const uint32_t sBaddr = smem_u32(sB);
    const uint32_t dA0 = sAaddr + (uint32_t)((rA       * LDA + cgA) * 4);
    const uint32_t dA1 = sAaddr + (uint32_t)(((rA + 64) * LDA + cgA) * 4);
    const uint32_t dB0 = sBaddr + (uint32_t)((krB * LDB + cgB) * 4);
    const float* srcA0 = Aptr + (size_t)gr0 * KDIM + cgA;
    const float* srcA1 = Aptr + (size_t)gr1 * KDIM + cgA;
    const float* srcB0 = Bw + (size_t)krB * NDIM + bn + cgB;

    constexpr int T = KDIM / BK;

    // warp layout: 8 warps = 4 (m) x 2 (n); warp tile 32x32
    const int wid = tid >> 5;
    const int wm = wid & 3, wn = wid >> 2;

    wmma::fragment<wmma::accumulator, 16, 16, 8, float> cf[2][2];
    #pragma unroll
    for (int i = 0; i < 2; i++)
        #pragma unroll
        for (int j = 0; j < 2; j++) wmma::fill_fragment(cf[i][j], 0.0f);

    // prefetch stage 0
    {
        CP_ASYNC16(dA0, srcA0);
        CP_ASYNC16(dA1, srcA1);
        CP_ASYNC16(dB0, srcB0);
        CP_COMMIT();
    }

    for (int t = 0; t < T; t++) {
        if (t + 1 < T) {
            const int k0 = (t + 1) * BK;
            const uint32_t so = (uint32_t)(((t + 1) & 1) ? A_STAGE_F * 4 : 0);
            const uint32_t sb = (uint32_t)(((t + 1) & 1) ? B_STAGE_F * 4 : 0);
            CP_ASYNC16(dA0 + so, srcA0 + k0);
            CP_ASYNC16(dA1 + so, srcA1 + k0);
            CP_ASYNC16(dB0 + sb, (const float*)(srcB0 + (size_t)k0 * NDIM));
            CP_COMMIT();
            CP_WAIT(1);
        } else {
            CP_WAIT(0);
        }
        __syncthreads();

        const float* At = sA + ((t & 1) ? A_STAGE_F : 0);
        const float* Bt = sB + ((t & 1) ? B_STAGE_F : 0);

        #pragma unroll
        for (int kk = 0; kk < BK; kk += 8) {
            wmma::fragment<wmma::matrix_a, 16, 16, 8, wmma::precision::tf32, wmma::row_major> af[2];
            wmma::fragment<wmma::matrix_b, 16, 16, 8, wmma::precision::tf32, wmma::row_major> bf[2];
            #pragma unroll
            for (int i = 0; i < 2; i++) {
                wmma::load_matrix_sync(af[i], At + (wm * 32 + i * 16) * LDA + kk, LDA);
                #pragma unroll
                for (int e = 0; e < af[i].num_elements; e++)
                    af[i].x[e] = wmma::__float_to_tf32(af[i].x[e]);
            }
            #pragma unroll
            for (int j = 0; j < 2; j++) {
                wmma::load_matrix_sync(bf[j], Bt + kk * LDB + wn * 32 + j * 16, LDB);
                #pragma unroll
                for (int e = 0; e < bf[j].num_elements; e++)
                    bf[j].x[e] = wmma::__float_to_tf32(bf[j].x[e]);
            }
            #pragma unroll
            for (int i = 0; i < 2; i++)
                #pragma unroll
                for (int j = 0; j < 2; j++)
                    wmma::mma_sync(cf[i][j], af[i], bf[j], cf[i][j]);
        }
        __syncthreads();
    }

    // store accumulators to smem C tile (aliases A/B buffers; all compute done)
    #pragma unroll
    for (int i = 0; i < 2; i++)
        #pragma unroll
        for (int j = 0; j < 2; j++)
            wmma::store_matrix_sync(sC + (wm * 32 + i * 16) * LDC + wn * 32 + j * 16,
                                    cf[i][j], LDC, wmma::mem_row_major);
    __syncthreads();

    // epilogue: 128 rows x 64 cols = 2048 float4; 8 per thread
    #pragma unroll
    for (int l = 0; l < 8; l++) {
        const int idx = tid + l * 256;
        const int row = idx >> 4;
        const int c   = (idx & 15) << 2;
        float4 v = *(const float4*)(sC + row * LDC + c);
        const int gc = bn + c;
        v.x += __ldg(bias + gc + 0);
        v.y += __ldg(bias + gc + 1);
        v.z += __ldg(bias + gc + 2);
        v.w += __ldg(bias + gc + 3);

        if constexpr (MODE == 0) {
            *(float4*)(g_qkv + (size_t)(bm + row) * QKVN + gc) = v;
        } else if constexpr (MODE == 1) {
            const int grow = map_win_to_global(bm + row);
            const size_t o = (size_t)grow * CDIM + gc;
            float4 r = *(const float4*)(resid + o);
            v.x += r.x; v.y += r.y; v.z += r.z; v.w += r.w;
            *(float4*)(g_x1 + o) = v;
        } else if constexpr (MODE == 2) {
            v.x = gelu_exact(v.x); v.y = gelu_exact(v.y);
            v.z = gelu_exact(v.z); v.w = gelu_exact(v.w);
            *(float4*)(g_h + (size_t)(bm + row) * HID + gc) = v;
        } else {
            const size_t o = (size_t)(bm + row) * CDIM + gc;
            float4 r = *(const float4*)(g_x1 + o);
            v.x += r.x; v.y += r.y; v.z += r.z; v.w += r.w;
            *(float4*)(Cout + o) = v;
        }
    }
}

// ---------------- LayerNorm: stats + normalize (one warp per token) ----------
__global__ void __launch_bounds__(256) ln_norm_k(const float* __restrict__ gamma,
                                                 const float* __restrict__ beta)
{
    const int r = blockIdx.x * 8 + (threadIdx.x >> 5);
    const int lane = threadIdx.x & 31;
    const float* p = g_x1 + (size_t)r * CDIM;
    float v[6];
    float s = 0.f, ss = 0.f;
    #pragma unroll
    for (int k = 0; k < 6; k++) {
        v[k] = p[lane + k * 32];
        s += v[k]; ss += v[k] * v[k];
    }
    #pragma unroll
    for (int o = 16; o; o >>= 1) {
        s  += __shfl_xor_sync(0xffffffffu, s,  o);
        ss += __shfl_xor_sync(0xffffffffu, ss, o);
    }
    const float mu = s * (1.f / 192.f);
    const float var = ss * (1.f / 192.f) - mu * mu;
    const float rs = rsqrtf(var + 1e-5f);
    float* q = g_x1n + (size_t)r * CDIM;
    #pragma unroll
    for (int k = 0; k < 6; k++) {
        const int c = lane + k * 32;
        q[c] = (v[k] - mu) * rs * __ldg(gamma + c) + __ldg(beta + c);
    }
}

// ---------------- attention: one block per (window, head), fp32 SIMT ---------
__global__ void __launch_bounds__(64) attn_k(const float* __restrict__ rpb)
{
    const int w = blockIdx.x, head = blockIdx.y, t = threadIdx.x;
    __shared__ float sK[64][32];
    __shared__ float sV[64][32];
    __shared__ float sS[64][65];
    __shared__ float sRp[225];
    __shared__ int   sReg[64];

    const float* base = g_qkv + (size_t)w * 64 * QKVN + head * HD;
    #pragma unroll
    for (int l = 0; l < 8; l++) {
        int i = t + l * 64;
        int n = i >> 3, dg = (i & 7) << 2;
        *(float4*)&sK[n][dg] = *(const float4*)(base + (size_t)n * QKVN + CDIM   + dg);
        *(float4*)&sV[n][dg] = *(const float4*)(base + (size_t)n * QKVN + 2*CDIM + dg);
    }
    for (int i = t; i < 225; i += 64) sRp[i] = rpb[i * NHEAD + head];
    {
        int rem = w & 255; int wh = rem >> 4, ww = rem & 15;
        int hs  = wh * 8 + (t >> 3);
        int wsc = ww * 8 + (t & 7);
        int rh = hs  < 120 ? 0 : (hs  < 124 ? 1 : 2);
        int rw = wsc < 120 ? 0 : (wsc < 124 ? 1 : 2);
        sReg[t] = rh * 3 + rw;
    }
    float qr[32];
    {
        const float* qp = g_qkv + ((size_t)w * 64 + t) * QKVN + head * HD;
        #pragma unroll
        for (int dg = 0; dg < 32; dg += 4) {
            float4 v = *(const float4*)(qp + dg);
            qr[dg] = v.x; qr[dg+1] = v.y; qr[dg+2] = v.z; qr[dg+3] = v.w;
        }
    }
    __syncthreads();

    const int i1 = t >> 3, j1 = t & 7;
    const int regt = sReg[t];
    const float scale = 0.17677669529663689f;

    for (int m = 0; m < 64; m++) {
        float acc = 0.f;
        #pragma unroll
        for (int d4 = 0; d4 < 8; d4++) {
            float4 kk = *(const float4*)&sK[m][d4 * 4];
            acc += qr[d4*4+0]*kk.x + qr[d4*4+1]*kk.y + qr[d4*4+2]*kk.z + qr[d4*4+3]*kk.w;
        }
        int i2 = m >> 3, j2 = m & 7;
        float b = sRp[(i1 - i2 + 7) * 15 + (j1 - j2 + 7)];
        float msk = (sReg[m] == regt) ? 0.f : -100.f;
        sS[t][m] = acc * scale + b + msk;
    }
    float mx = -1e30f;
    for (int m = 0; m < 64; m++) mx = fmaxf(mx, sS[t][m]);
    float sum = 0.f;
    for (int m = 0; m < 64; m++) { float e = __expf(sS[t][m] - mx); sS[t][m] = e; sum += e; }
    float inv = 1.f / sum;

    float acc[32];
    #pragma unroll
    for (int d = 0; d < 32; d++) acc[d] = 0.f;
    for (int m = 0; m < 64; m++) {
        float p = sS[t][m];
        #pragma unroll
        for (int d4 = 0; d4 < 8; d4++) {
            float4 vv = *(const float4*)&sV[m][d4 * 4];
            acc[d4*4+0] += p * vv.x; acc[d4*4+1] += p * vv.y;
            acc[d4*4+2] += p * vv.z; acc[d4*4+3] += p * vv.w;
        }
    }
    float* op = g_attnout + ((size_t)w * 64 + t) * CDIM + head * HD;
    #pragma unroll
    for (int dg = 0; dg < 32; dg += 4)
        *(float4*)(op + dg) = make_float4(acc[dg]*inv, acc[dg+1]*inv, acc[dg+2]*inv, acc[dg+3]*inv);
}

// ---------------- launch -----------------------------------------------------
extern "C" void kernel_launch(void* const* d_in, const int* in_sizes, int n_in,
                              void* d_out, int out_size)
{
    const float* x       = (const float*)d_in[0];
    const float* qkv_w   = (const float*)d_in[1];
    const float* qkv_b   = (const float*)d_in[2];
    const float* proj_w  = (const float*)d_in[3];
    const float* proj_b  = (const float*)d_in[4];
    const float* rpb     = (const float*)d_in[5];
    const float* norm2_g = (const float*)d_in[6];
    const float* norm2_b = (const float*)d_in[7];
    const float* mlp_w1  = (const float*)d_in[8];
    const float* mlp_b1  = (const float*)d_in[9];
    const float* mlp_w2  = (const float*)d_in[10];
    const float* mlp_b2  = (const float*)d_in[11];
    float* out = (float*)d_out;

    // 1) QKV = gather(x) @ qkv_w + b   (window-ordered output)
    gemm_wmma<192, 576, 0><<<dim3(9, 1024), 256>>>(x, qkv_w, qkv_b, nullptr, nullptr);
    // 2) windowed attention (rel-pos bias + shift mask + softmax)
    attn_k<<<dim3(NWIN, NHEAD), 64>>>(rpb);
    // 3) proj + scatter + residual -> g_x1
    gemm_wmma<192, 192, 1><<<dim3(3, 1024), 256>>>(nullptr, proj_w, proj_b, x, nullptr);
    // 4) LayerNorm(g_x1) -> g_x1n
    ln_norm_k<<<TOK / 8, 256>>>(norm2_g, norm2_b);
    // 5) fc1 + GELU -> g_h
    gemm_wmma<192, 768, 2><<<dim3(12, 1024), 256>>>(nullptr, mlp_w1, mlp_b1, nullptr, nullptr);
    // 6) fc2 + residual -> out
    gemm_wmma<768, 192, 3><<<dim3(3, 1024), 256>>>(nullptr, mlp_w2, mlp_b2, nullptr, out);
}

// round 4
// speedup vs baseline: 3.3544x; 2.3679x over previous
#include <cuda_runtime.h>
#include <cuda_bf16.h>
#include <mma.h>
#include <cstdint>
#include <math.h>

using namespace nvcuda;
typedef __nv_bfloat16 bf16;

// Problem constants (fixed shapes)
#define TOK   131072      // B*H*W = 8*128*128
#define CDIM  192
#define HID   768
#define QKVN  576
#define NHEAD 6
#define SS    4
#define NWIN  2048        // B * 16 * 16

// GEMM tiling
#define BM 128
#define BN 64
#define BK 32
#define LDA 40            // A tile ld (bf16), 80B rows (16B-aligned, padded)
#define LDB 72            // B tile ld (bf16), 144B rows
#define LDC 68            // C tile ld (fp32)
#define A_STAGE_B (BM * LDA * 2)      // 10240 bytes
#define B_STAGE_B (BK * LDB * 2)      // 4608 bytes
#define SMEM_BYTES (BM * LDC * 4)     // 34816 (C tile unions over 2-stage A/B = 29696)

// ---------------- scratch (device globals; no allocations allowed) ----------
__device__ bf16  g_xbf[TOK * CDIM];        // bf16 copy of x (QKV GEMM A)
__device__ bf16  g_qkv[TOK * QKVN];        // window-ordered, bf16
__device__ bf16  g_attnout[TOK * CDIM];    // window-ordered, bf16
__device__ float g_x1[TOK * CDIM];         // x + attn branch (fp32, global order)
__device__ bf16  g_x1n[TOK * CDIM];        // LN(x1)*g+b, bf16
__device__ bf16  g_h[TOK * HID];           // gelu(fc1), bf16
__device__ bf16  g_wqkv[CDIM * QKVN];      // bf16 weights, original [K][N] layout
__device__ bf16  g_wproj[CDIM * CDIM];
__device__ bf16  g_w1[CDIM * HID];
__device__ bf16  g_w2[HID * CDIM];

// ---------------- helpers ----------------------------------------------------
__device__ __forceinline__ uint32_t smem_u32(const void* p) {
    uint32_t a;
    asm("{ .reg .u64 t; cvta.to.shared.u64 t, %1; cvt.u32.u64 %0, t; }" : "=r"(a) : "l"(p));
    return a;
}
#define CP_ASYNC16(dst, src) \
    asm volatile("cp.async.cg.shared.global [%0], [%1], 16;" :: "r"(dst), "l"(src))
#define CP_COMMIT() asm volatile("cp.async.commit_group;" ::: "memory")
#define CP_WAIT(n)  asm volatile("cp.async.wait_group %0;" :: "n"(n) : "memory")

__device__ __forceinline__ int map_win_to_global(int r) {
    int w = r >> 6, n = r & 63;
    int b = w >> 8, rem = w & 255;
    int wh = rem >> 4, ww = rem & 15;
    int i = n >> 3, j = n & 7;
    int h  = (wh * 8 + i + SS) & 127;
    int wc = (ww * 8 + j + SS) & 127;
    return (b << 14) + (h << 7) + wc;
}
__device__ __forceinline__ float gelu_exact(float v) {
    return 0.5f * v * (1.0f + erff(v * 0.70710678118654752440f));
}
__device__ __forceinline__ uint32_t pack_bf2(float a, float b) {
    __nv_bfloat162 h = __floats2bfloat162_rn(a, b);
    return *(uint32_t*)&h;
}

// ---------------- fp32 -> bf16 conversion kernels -----------------------------
__global__ void __launch_bounds__(256) conv_x_k(const float* __restrict__ src) {
    const size_t i = ((size_t)blockIdx.x * 256 + threadIdx.x) * 8;
    float4 v0 = *(const float4*)(src + i);
    float4 v1 = *(const float4*)(src + i + 4);
    uint4 o;
    o.x = pack_bf2(v0.x, v0.y); o.y = pack_bf2(v0.z, v0.w);
    o.z = pack_bf2(v1.x, v1.y); o.w = pack_bf2(v1.z, v1.w);
    *(uint4*)(g_xbf + i) = o;
}
template<int W>
__global__ void __launch_bounds__(256) conv_w_k(const float* __restrict__ src, int n) {
    bf16* dst;
    if      constexpr (W == 0) dst = g_wqkv;
    else if constexpr (W == 1) dst = g_wproj;
    else if constexpr (W == 2) dst = g_w1;
    else                       dst = g_w2;
    for (int i = blockIdx.x * 256 + threadIdx.x; i < n; i += gridDim.x * 256)
        dst[i] = __float2bfloat16_rn(src[i]);
}

// ---------------- WMMA bf16 GEMM ----------------------------------------------
// C[M,N] = A[M,K] @ B[K,N] (+bias, +epilogue). A,B bf16 row-major in gmem.
// MODE: 0=QKV(gather A rows; out bf16 g_qkv)  1=PROJ(scatter+resid fp32 -> g_x1)
//       2=FC1(gelu -> bf16 g_h)               3=FC2(+resid g_x1 -> fp32 Cout)
template<int KDIM, int NDIM, int MODE>
__global__ void __launch_bounds__(128) gemm_bf(
    const float* __restrict__ bias,
    const float* __restrict__ resid,   // MODE1: x (fp32)
    float* __restrict__ Cout)          // MODE3: final output
{
    __shared__ __align__(16) unsigned char smem[SMEM_BYTES];
    bf16* sA = (bf16*)smem;                            // [2][BM*LDA]
    bf16* sB = (bf16*)(smem + 2 * A_STAGE_B);          // [2][BK*LDB]
    float* sC = (float*)smem;

    const int tid = threadIdx.x;
    const int bm = blockIdx.y * BM;
    const int bn = blockIdx.x * BN;

    const bf16* Aptr;
    const bf16* Bptr;
    if      constexpr (MODE == 0) { Aptr = g_xbf;     Bptr = g_wqkv; }
    else if constexpr (MODE == 1) { Aptr = g_attnout; Bptr = g_wproj; }
    else if constexpr (MODE == 2) { Aptr = g_x1n;     Bptr = g_w1; }
    else                          { Aptr = g_h;       Bptr = g_w2; }

    // A: thread t owns row t, 4 x 16B chunks (32 bf16)
    int grA;
    if constexpr (MODE == 0) grA = map_win_to_global(bm + tid);
    else                     grA = bm + tid;
    const bf16* srcA = Aptr + (size_t)grA * KDIM;
    const uint32_t dA = smem_u32(sA) + (uint32_t)(tid * LDA * 2);

    // B: 32 rows x 64 bf16 = 4KB = 256 chunks; thread handles chunks tid, tid+128
    const int bR0 = tid >> 3,        bC0 = (tid & 7) * 8;
    const int bR1 = (tid + 128) >> 3, bC1 = (tid & 7) * 8;   // rows 0..15 / 16..31
    const bf16* srcB0 = Bptr + (size_t)bR0 * NDIM + bn + bC0;
    const bf16* srcB1 = Bptr + (size_t)bR1 * NDIM + bn + bC1;
    const uint32_t dB0 = smem_u32(sB) + (uint32_t)((bR0 * LDB + bC0) * 2);
    const uint32_t dB1 = smem_u32(sB) + (uint32_t)((bR1 * LDB + bC1) * 2);

    constexpr int T = KDIM / BK;
    const int wid = tid >> 5;
    const int wm = wid & 1, wn = wid >> 1;   // 2x2 warps, warp tile 64x32

    wmma::fragment<wmma::accumulator, 16, 16, 16, float> cf[4][2];
    #pragma unroll
    for (int i = 0; i < 4; i++)
        #pragma unroll
        for (int j = 0; j < 2; j++) wmma::fill_fragment(cf[i][j], 0.0f);

    // prefetch stage 0
    #pragma unroll
    for (int c = 0; c < 4; c++) CP_ASYNC16(dA + c * 16, srcA + c * 8);
    CP_ASYNC16(dB0, srcB0);
    CP_ASYNC16(dB1, srcB1);
    CP_COMMIT();

    for (int t = 0; t < T; t++) {
        if (t + 1 < T) {
            const int k0 = (t + 1) * BK;
            const uint32_t soA = ((t + 1) & 1) ? A_STAGE_B : 0;
            const uint32_t soB = ((t + 1) & 1) ? B_STAGE_B : 0;
            #pragma unroll
            for (int c = 0; c < 4; c++) CP_ASYNC16(dA + soA + c * 16, srcA + k0 + c * 8);
            CP_ASYNC16(dB0 + soB, srcB0 + (size_t)k0 * NDIM);
            CP_ASYNC16(dB1 + soB, srcB1 + (size_t)k0 * NDIM);
            CP_COMMIT();
            CP_WAIT(1);
        } else {
            CP_WAIT(0);
        }
        __syncthreads();

        const bf16* At = sA + ((t & 1) ? BM * LDA : 0);
        const bf16* Bt = sB + ((t & 1) ? BK * LDB : 0);

        #pragma unroll
        for (int kk = 0; kk < BK; kk += 16) {
            wmma::fragment<wmma::matrix_a, 16, 16, 16, bf16, wmma::row_major> af[4];
            wmma::fragment<wmma::matrix_b, 16, 16, 16, bf16, wmma::row_major> bf_[2];
            #pragma unroll
            for (int i = 0; i < 4; i++)
                wmma::load_matrix_sync(af[i], At + (wm * 64 + i * 16) * LDA + kk, LDA);
            #pragma unroll
            for (int j = 0; j < 2; j++)
                wmma::load_matrix_sync(bf_[j], Bt + kk * LDB + wn * 32 + j * 16, LDB);
            #pragma unroll
            for (int i = 0; i < 4; i++)
                #pragma unroll
                for (int j = 0; j < 2; j++)
                    wmma::mma_sync(cf[i][j], af[i], bf_[j], cf[i][j]);
        }
        __syncthreads();
    }

    // accumulators -> smem C tile (aliases A/B; compute done)
    #pragma unroll
    for (int i = 0; i < 4; i++)
        #pragma unroll
        for (int j = 0; j < 2; j++)
            wmma::store_matrix_sync(sC + (wm * 64 + i * 16) * LDC + wn * 32 + j * 16,
                                    cf[i][j], LDC, wmma::mem_row_major);
    __syncthreads();

    // epilogue: thread t owns full output row t (64 cols)
    const int row = tid;
    const int m = bm + row;
    float v[64];
    #pragma unroll
    for (int c4 = 0; c4 < 16; c4++) {
        float4 w4 = *(const float4*)(sC + row * LDC + c4 * 4);
        v[c4*4+0] = w4.x + __ldg(bias + bn + c4*4 + 0);
        v[c4*4+1] = w4.y + __ldg(bias + bn + c4*4 + 1);
        v[c4*4+2] = w4.z + __ldg(bias + bn + c4*4 + 2);
        v[c4*4+3] = w4.w + __ldg(bias + bn + c4*4 + 3);
    }

    if constexpr (MODE == 0) {
        bf16* dst = g_qkv + (size_t)m * QKVN + bn;
        #pragma unroll
        for (int g = 0; g < 8; g++) {
            uint4 o;
            o.x = pack_bf2(v[g*8+0], v[g*8+1]); o.y = pack_bf2(v[g*8+2], v[g*8+3]);
            o.z = pack_bf2(v[g*8+4], v[g*8+5]); o.w = pack_bf2(v[g*8+6], v[g*8+7]);
            *(uint4*)(dst + g * 8) = o;
        }
    } else if constexpr (MODE == 1) {
        const int grow = map_win_to_global(m);
        const size_t o = (size_t)grow * CDIM + bn;
        #pragma unroll
        for (int c4 = 0; c4 < 16; c4++) {
            float4 r = *(const float4*)(resid + o + c4 * 4);
            *(float4*)(g_x1 + o + c4 * 4) =
                make_float4(v[c4*4+0] + r.x, v[c4*4+1] + r.y, v[c4*4+2] + r.z, v[c4*4+3] + r.w);
        }
    } else if constexpr (MODE == 2) {
        bf16* dst = g_h + (size_t)m * HID + bn;
        #pragma unroll
        for (int g = 0; g < 8; g++) {
            uint4 o;
            o.x = pack_bf2(gelu_exact(v[g*8+0]), gelu_exact(v[g*8+1]));
            o.y = pack_bf2(gelu_exact(v[g*8+2]), gelu_exact(v[g*8+3]));
            o.z = pack_bf2(gelu_exact(v[g*8+4]), gelu_exact(v[g*8+5]));
            o.w = pack_bf2(gelu_exact(v[g*8+6]), gelu_exact(v[g*8+7]));
            *(uint4*)(dst + g * 8) = o;
        }
    } else {
        const size_t o = (size_t)m * CDIM + bn;
        #pragma unroll
        for (int c4 = 0; c4 < 16; c4++) {
            float4 r = *(const float4*)(g_x1 + o + c4 * 4);
            *(float4*)(Cout + o + c4 * 4) =
                make_float4(v[c4*4+0] + r.x, v[c4*4+1] + r.y, v[c4*4+2] + r.z, v[c4*4+3] + r.w);
        }
    }
}

// ---------------- LayerNorm: one warp per token, bf16 out ---------------------
__global__ void __launch_bounds__(256) ln_norm_k(const float* __restrict__ gamma,
                                                 const float* __restrict__ beta)
{
    const int r = blockIdx.x * 8 + (threadIdx.x >> 5);
    const int lane = threadIdx.x & 31;
    const float* p = g_x1 + (size_t)r * CDIM;
    float v[6];
    float s = 0.f, ss = 0.f;
    #pragma unroll
    for (int k = 0; k < 6; k++) {
        v[k] = p[lane + k * 32];
        s += v[k]; ss += v[k] * v[k];
    }
    #pragma unroll
    for (int o = 16; o; o >>= 1) {
        s  += __shfl_xor_sync(0xffffffffu, s,  o);
        ss += __shfl_xor_sync(0xffffffffu, ss, o);
    }
    const float mu = s * (1.f / 192.f);
    const float var = ss * (1.f / 192.f) - mu * mu;
    const float rs = rsqrtf(var + 1e-5f);
    bf16* q = g_x1n + (size_t)r * CDIM;
    #pragma unroll
    for (int k = 0; k < 6; k++) {
        const int c = lane + k * 32;
        q[c] = __float2bfloat16_rn((v[k] - mu) * rs * __ldg(gamma + c) + __ldg(beta + c));
    }
}

// ---------------- attention: one block per (window, head), bf16 in/out --------
__global__ void __launch_bounds__(64) attn_k(const float* __restrict__ rpb)
{
    const int w = blockIdx.x, head = blockIdx.y, t = threadIdx.x;
    __shared__ float sK[64][32];
    __shared__ float sV[64][32];
    __shared__ float sS[64][65];
    __shared__ float sRp[225];
    __shared__ int   sReg[64];

    const bf16* base = g_qkv + (size_t)w * 64 * QKVN + head * 32;
    #pragma unroll
    for (int l = 0; l < 4; l++) {               // 256 chunks of 8 bf16 / 64 threads
        int i = t + l * 64;
        int n = i >> 2, cg = (i & 3) * 8;
        uint4 kc = *(const uint4*)(base + (size_t)n * QKVN + CDIM     + cg);
        uint4 vc = *(const uint4*)(base + (size_t)n * QKVN + 2*CDIM   + cg);
        const __nv_bfloat162* kp = (const __nv_bfloat162*)&kc;
        const __nv_bfloat162* vp = (const __nv_bfloat162*)&vc;
        #pragma unroll
        for (int u = 0; u < 4; u++) {
            float2 kf = __bfloat1622float2(kp[u]);
            float2 vf = __bfloat1622float2(vp[u]);
            sK[n][cg + u*2 + 0] = kf.x; sK[n][cg + u*2 + 1] = kf.y;
            sV[n][cg + u*2 + 0] = vf.x; sV[n][cg + u*2 + 1] = vf.y;
        }
    }
    for (int i = t; i < 225; i += 64) sRp[i] = rpb[i * NHEAD + head];
    {
        int rem = w & 255; int wh = rem >> 4, ww = rem & 15;
        int hs  = wh * 8 + (t >> 3);
        int wsc = ww * 8 + (t & 7);
        int rh = hs  < 120 ? 0 : (hs  < 124 ? 1 : 2);
        int rw = wsc < 120 ? 0 : (wsc < 124 ? 1 : 2);
        sReg[t] = rh * 3 + rw;
    }
    float qr[32];
    {
        const bf16* qp = g_qkv + ((size_t)w * 64 + t) * QKVN + head * 32;
        #pragma unroll
        for (int g = 0; g < 4; g++) {
            uint4 qc = *(const uint4*)(qp + g * 8);
            const __nv_bfloat162* pp = (const __nv_bfloat162*)&qc;
            #pragma unroll
            for (int u = 0; u < 4; u++) {
                float2 f = __bfloat1622float2(pp[u]);
                qr[g*8 + u*2 + 0] = f.x; qr[g*8 + u*2 + 1] = f.y;
            }
        }
    }
    __syncthreads();

    const int i1 = t >> 3, j1 = t & 7;
    const int regt = sReg[t];
    const float scale = 0.17677669529663689f;

    for (int m = 0; m < 64; m++) {
        float acc = 0.f;
        #pragma unroll
        for (int d4 = 0; d4 < 8; d4++) {
            float4 kk = *(const float4*)&sK[m][d4 * 4];
            acc += qr[d4*4+0]*kk.x + qr[d4*4+1]*kk.y + qr[d4*4+2]*kk.z + qr[d4*4+3]*kk.w;
        }
        int i2 = m >> 3, j2 = m & 7;
        float b = sRp[(i1 - i2 + 7) * 15 + (j1 - j2 + 7)];
        float msk = (sReg[m] == regt) ? 0.f : -100.f;
        sS[t][m] = acc * scale + b + msk;
    }
    float mx = -1e30f;
    for (int m = 0; m < 64; m++) mx = fmaxf(mx, sS[t][m]);
    float sum = 0.f;
    for (int m = 0; m < 64; m++) { float e = __expf(sS[t][m] - mx); sS[t][m] = e; sum += e; }
    float inv = 1.f / sum;

    float acc[32];
    #pragma unroll
    for (int d = 0; d < 32; d++) acc[d] = 0.f;
    for (int m = 0; m < 64; m++) {
        float p = sS[t][m];
        #pragma unroll
        for (int d4 = 0; d4 < 8; d4++) {
            float4 vv = *(const float4*)&sV[m][d4 * 4];
            acc[d4*4+0] += p * vv.x; acc[d4*4+1] += p * vv.y;
            acc[d4*4+2] += p * vv.z; acc[d4*4+3] += p * vv.w;
        }
    }
    bf16* op = g_attnout + ((size_t)w * 64 + t) * CDIM + head * 32;
    #pragma unroll
    for (int g = 0; g < 4; g++) {
        uint2 o;
        o.x = pack_bf2(acc[g*8+0]*inv, acc[g*8+1]*inv);
        o.y = pack_bf2(acc[g*8+2]*inv, acc[g*8+3]*inv);
        uint2 o2;
        o2.x = pack_bf2(acc[g*8+4]*inv, acc[g*8+5]*inv);
        o2.y = pack_bf2(acc[g*8+6]*inv, acc[g*8+7]*inv);
        *(uint2*)(op + g * 8)     = o;
        *(uint2*)(op + g * 8 + 4) = o2;
    }
}

// ---------------- launch -----------------------------------------------------
extern "C" void kernel_launch(void* const* d_in, const int* in_sizes, int n_in,
                              void* d_out, int out_size)
{
    const float* x       = (const float*)d_in[0];
    const float* qkv_w   = (const float*)d_in[1];
    const float* qkv_b   = (const float*)d_in[2];
    const float* proj_w  = (const float*)d_in[3];
    const float* proj_b  = (const float*)d_in[4];
    const float* rpb     = (const float*)d_in[5];
    const float* norm2_g = (const float*)d_in[6];
    const float* norm2_b = (const float*)d_in[7];
    const float* mlp_w1  = (const float*)d_in[8];
    const float* mlp_b1  = (const float*)d_in[9];
    const float* mlp_w2  = (const float*)d_in[10];
    const float* mlp_b2  = (const float*)d_in[11];
    float* out = (float*)d_out;

    // precision conversions
    conv_x_k<<<TOK * CDIM / (256 * 8), 256>>>(x);
    conv_w_k<0><<<108, 256>>>(qkv_w,  CDIM * QKVN);
    conv_w_k<1><<<36,  256>>>(proj_w, CDIM * CDIM);
    conv_w_k<2><<<144, 256>>>(mlp_w1, CDIM * HID);
    conv_w_k<3><<<144, 256>>>(mlp_w2, HID * CDIM);

    // 1) QKV = gather(x) @ qkv_w + b  -> bf16 g_qkv (window order)
    gemm_bf<192, 576, 0><<<dim3(9, 1024), 128>>>(qkv_b, nullptr, nullptr);
    // 2) windowed attention -> bf16 g_attnout
    attn_k<<<dim3(NWIN, NHEAD), 64>>>(rpb);
    // 3) proj + scatter + residual -> fp32 g_x1
    gemm_bf<192, 192, 1><<<dim3(3, 1024), 128>>>(proj_b, x, nullptr);
    // 4) LayerNorm(g_x1) -> bf16 g_x1n
    ln_norm_k<<<TOK / 8, 256>>>(norm2_g, norm2_b);
    // 5) fc1 + GELU -> bf16 g_h
    gemm_bf<192, 768, 2><<<dim3(12, 1024), 128>>>(mlp_b1, nullptr, nullptr);
    // 6) fc2 + residual -> fp32 out
    gemm_bf<768, 192, 3><<<dim3(3, 1024), 128>>>(mlp_b2, nullptr, out);
}